// round 1
// baseline (speedup 1.0000x reference)
#include <cuda_runtime.h>
#include <math.h>

#define B_   2048
#define DIN_ 768
#define D_   512
#define H_   8
#define HD_  64
#define L_   3
#define P_   40
#define Q_   128
#define EPSF 1e-5f

// ---------------- scratch (device globals; no allocation allowed) ----------------
__device__ float g_feat0[B_ * D_];
__device__ float g_feat [B_ * D_];
__device__ float g_buf1 [B_ * D_];
__device__ float g_buf2 [B_ * D_];
__device__ float g_qkv  [B_ * 3 * D_];
__device__ float g_scores[(size_t)H_ * B_ * B_];   // 134 MB
__device__ float g_z    [B_ * Q_];

// ---------------- GEMM TN: C = alpha*(A @ W^T) [+bias] [+res] [relu] ----------------
// A: [M,K] lda ; W: [N,K] ldw ; C: [M,N] ldc. M,N implied by grid (64x64 tiles).
// EPI: 0 = bias(optional), 1 = bias+relu, 2 = bias + residual add
template<int EPI>
__global__ __launch_bounds__(256)
void gemm_tn(const float* __restrict__ A, const float* __restrict__ W,
             const float* __restrict__ bias, const float* __restrict__ res,
             float* __restrict__ C, int K, int lda, int ldw, int ldc,
             long sA, long sW, long sC, float alpha)
{
    A += (long)blockIdx.z * sA;
    W += (long)blockIdx.z * sW;
    C += (long)blockIdx.z * sC;
    __shared__ float As[16][65];
    __shared__ float Ws[16][65];
    const int tid = threadIdx.x;
    const int tx = tid & 15, ty = tid >> 4;
    const int m0 = blockIdx.y * 64, n0 = blockIdx.x * 64;
    const int col = tid & 15, row0 = tid >> 4;
    float acc[4][4] = {};
    for (int k0 = 0; k0 < K; k0 += 16) {
        #pragma unroll
        for (int r = 0; r < 4; r++) {
            int row = row0 + r * 16;
            As[col][row] = A[(size_t)(m0 + row) * lda + k0 + col];
            Ws[col][row] = W[(size_t)(n0 + row) * ldw + k0 + col];
        }
        __syncthreads();
        #pragma unroll
        for (int kk = 0; kk < 16; kk++) {
            float a[4], b[4];
            #pragma unroll
            for (int i = 0; i < 4; i++) a[i] = As[kk][ty * 4 + i];
            #pragma unroll
            for (int j = 0; j < 4; j++) b[j] = Ws[kk][tx * 4 + j];
            #pragma unroll
            for (int i = 0; i < 4; i++)
                #pragma unroll
                for (int j = 0; j < 4; j++)
                    acc[i][j] = fmaf(a[i], b[j], acc[i][j]);
        }
        __syncthreads();
    }
    #pragma unroll
    for (int i = 0; i < 4; i++) {
        int m = m0 + ty * 4 + i;
        #pragma unroll
        for (int j = 0; j < 4; j++) {
            int n = n0 + tx * 4 + j;
            float v = acc[i][j] * alpha;
            if (bias) v += bias[n];
            if (EPI == 1) v = fmaxf(v, 0.f);
            if (EPI == 2) v += res[(size_t)m * ldc + n];
            C[(size_t)m * ldc + n] = v;
        }
    }
}

// ---------------- GEMM NN: C = A @ B  (A:[M,K] lda, B:[K,N] ldb, C:[M,N] ldc) ----------------
__global__ __launch_bounds__(256)
void gemm_nn(const float* __restrict__ A, const float* __restrict__ Bm,
             float* __restrict__ C, int K, int lda, int ldb, int ldc,
             long sA, long sB, long sC)
{
    A  += (long)blockIdx.z * sA;
    Bm += (long)blockIdx.z * sB;
    C  += (long)blockIdx.z * sC;
    __shared__ float As[16][65];
    __shared__ float Bs[16][65];
    const int tid = threadIdx.x;
    const int tx = tid & 15, ty = tid >> 4;
    const int m0 = blockIdx.y * 64, n0 = blockIdx.x * 64;
    float acc[4][4] = {};
    for (int k0 = 0; k0 < K; k0 += 16) {
        {
            int col = tid & 15, row0 = tid >> 4;
            #pragma unroll
            for (int r = 0; r < 4; r++) {
                int row = row0 + r * 16;
                As[col][row] = A[(size_t)(m0 + row) * lda + k0 + col];
            }
            int nn = tid & 63, kr = tid >> 6;
            #pragma unroll
            for (int r = 0; r < 4; r++) {
                int kk = kr + r * 4;
                Bs[kk][nn] = Bm[(size_t)(k0 + kk) * ldb + n0 + nn];
            }
        }
        __syncthreads();
        #pragma unroll
        for (int kk = 0; kk < 16; kk++) {
            float a[4], b[4];
            #pragma unroll
            for (int i = 0; i < 4; i++) a[i] = As[kk][ty * 4 + i];
            #pragma unroll
            for (int j = 0; j < 4; j++) b[j] = Bs[kk][tx * 4 + j];
            #pragma unroll
            for (int i = 0; i < 4; i++)
                #pragma unroll
                for (int j = 0; j < 4; j++)
                    acc[i][j] = fmaf(a[i], b[j], acc[i][j]);
        }
        __syncthreads();
    }
    #pragma unroll
    for (int i = 0; i < 4; i++) {
        int m = m0 + ty * 4 + i;
        #pragma unroll
        for (int j = 0; j < 4; j++) {
            int n = n0 + tx * 4 + j;
            C[(size_t)m * ldc + n] = acc[i][j];
        }
    }
}

// ---------------- softmax over rows of length 2048 (one block/row) ----------------
__global__ __launch_bounds__(256)
void softmax2048(float* __restrict__ S)
{
    float* row = S + (size_t)blockIdx.x * 2048;
    const int t = threadIdx.x;
    float v[8];
    float mx = -3.4e38f;
    #pragma unroll
    for (int i = 0; i < 8; i++) { v[i] = row[t + i * 256]; mx = fmaxf(mx, v[i]); }
    __shared__ float sm[8];
    #pragma unroll
    for (int o = 16; o > 0; o >>= 1) mx = fmaxf(mx, __shfl_xor_sync(0xffffffffu, mx, o));
    if ((t & 31) == 0) sm[t >> 5] = mx;
    __syncthreads();
    mx = fmaxf(fmaxf(fmaxf(sm[0], sm[1]), fmaxf(sm[2], sm[3])),
               fmaxf(fmaxf(sm[4], sm[5]), fmaxf(sm[6], sm[7])));
    float s = 0.f;
    #pragma unroll
    for (int i = 0; i < 8; i++) { v[i] = __expf(v[i] - mx); s += v[i]; }
    __syncthreads();
    #pragma unroll
    for (int o = 16; o > 0; o >>= 1) s += __shfl_xor_sync(0xffffffffu, s, o);
    if ((t & 31) == 0) sm[t >> 5] = s;
    __syncthreads();
    s = sm[0] + sm[1] + sm[2] + sm[3] + sm[4] + sm[5] + sm[6] + sm[7];
    float inv = 1.0f / s;
    #pragma unroll
    for (int i = 0; i < 8; i++) row[t + i * 256] = v[i] * inv;
}

// ---------------- per-row normalize (LN if AFFINE, InstanceNorm otherwise) ----------------
// dst = norm(src)[*w+b][+addv]; optional dst2 copy
template<int N, bool AFFINE, bool ADD>
__global__ __launch_bounds__(128)
void rownorm(const float* __restrict__ src, const float* __restrict__ addv,
             const float* __restrict__ w, const float* __restrict__ bb,
             float* __restrict__ dst, float* __restrict__ dst2)
{
    constexpr int NPT = N / 128;
    const size_t base = (size_t)blockIdx.x * N;
    const int t = threadIdx.x;
    float v[NPT];
    float s = 0.f;
    #pragma unroll
    for (int i = 0; i < NPT; i++) { v[i] = src[base + t + i * 128]; s += v[i]; }
    __shared__ float sm[4];
    #pragma unroll
    for (int o = 16; o > 0; o >>= 1) s += __shfl_xor_sync(0xffffffffu, s, o);
    if ((t & 31) == 0) sm[t >> 5] = s;
    __syncthreads();
    s = sm[0] + sm[1] + sm[2] + sm[3];
    const float mean = s * (1.0f / N);
    float q = 0.f;
    #pragma unroll
    for (int i = 0; i < NPT; i++) { float d = v[i] - mean; q += d * d; }
    __syncthreads();
    #pragma unroll
    for (int o = 16; o > 0; o >>= 1) q += __shfl_xor_sync(0xffffffffu, q, o);
    if ((t & 31) == 0) sm[t >> 5] = q;
    __syncthreads();
    q = sm[0] + sm[1] + sm[2] + sm[3];
    const float r = rsqrtf(q * (1.0f / N) + EPSF);
    #pragma unroll
    for (int i = 0; i < NPT; i++) {
        int c = t + i * 128;
        float y = (v[i] - mean) * r;
        if (AFFINE) y = y * w[c] + bb[c];
        if (ADD)    y += addv[base + c];
        dst[base + c] = y;
        if (dst2) dst2[base + c] = y;
    }
}

// ---------------- cdist to prototypes, min over P, logits ----------------
__global__ __launch_bounds__(128)
void cdist_logits(const float* __restrict__ z, const float* __restrict__ hi,
                  const float* __restrict__ neg, float* __restrict__ out)
{
    __shared__ float zr[Q_];
    __shared__ float dist[128];
    const int b = blockIdx.x, t = threadIdx.x;
    zr[t] = z[(size_t)b * Q_ + t];
    dist[t] = 3.4e38f;
    __syncthreads();
    if (t < P_) {
        const float* p = hi + (size_t)t * Q_;
        float s = 0.f;
        #pragma unroll 8
        for (int d = 0; d < Q_; d++) { float df = zr[d] - p[d]; s = fmaf(df, df, s); }
        dist[t] = sqrtf(s);
    } else if (t >= 64 && t < 64 + P_) {
        const float* p = neg + (size_t)(t - 64) * Q_;
        float s = 0.f;
        #pragma unroll 8
        for (int d = 0; d < Q_; d++) { float df = zr[d] - p[d]; s = fmaf(df, df, s); }
        dist[t] = sqrtf(s);
    }
    __syncthreads();
    if (t == 0) {
        float m = 3.4e38f;
        for (int i = 0; i < P_; i++) m = fminf(m, dist[i]);
        out[b * 2 + 1] = -m;      // -positive_dist
    }
    if (t == 32) {
        float m = 3.4e38f;
        for (int i = 0; i < P_; i++) m = fminf(m, dist[64 + i]);
        out[b * 2 + 0] = -m;      // -negative_dist
    }
}

// ---------------- host driver ----------------
extern "C" void kernel_launch(void* const* d_in, const int* in_sizes, int n_in,
                              void* d_out, int out_size)
{
    const float* x        = (const float*)d_in[0];
    const float* reduce_w = (const float*)d_in[1];
    const float* reduce_b = (const float*)d_in[2];
    const float* in_w     = (const float*)d_in[3];
    const float* in_b     = (const float*)d_in[4];
    const float* out_w    = (const float*)d_in[5];
    const float* out_b    = (const float*)d_in[6];
    const float* ff1_w    = (const float*)d_in[7];
    const float* ff1_b    = (const float*)d_in[8];
    const float* ff2_w    = (const float*)d_in[9];
    const float* ff2_b    = (const float*)d_in[10];
    const float* ln1_w    = (const float*)d_in[11];
    const float* ln1_b    = (const float*)d_in[12];
    const float* ln2_w    = (const float*)d_in[13];
    const float* ln2_b    = (const float*)d_in[14];
    const float* mlp_w1   = (const float*)d_in[15];
    const float* mlp_b1   = (const float*)d_in[16];
    const float* mlp_w2   = (const float*)d_in[17];
    const float* mlp_b2   = (const float*)d_in[18];
    const float* mlp_w3   = (const float*)d_in[19];
    const float* mlp_b3   = (const float*)d_in[20];
    const float* highlights = (const float*)d_in[21];
    const float* negatives  = (const float*)d_in[22];
    float* out = (float*)d_out;

    float *feat0, *feat, *buf1, *buf2, *qkv, *scores, *z;
    cudaGetSymbolAddress((void**)&feat0, g_feat0);
    cudaGetSymbolAddress((void**)&feat,  g_feat);
    cudaGetSymbolAddress((void**)&buf1,  g_buf1);
    cudaGetSymbolAddress((void**)&buf2,  g_buf2);
    cudaGetSymbolAddress((void**)&qkv,   g_qkv);
    cudaGetSymbolAddress((void**)&scores,g_scores);
    cudaGetSymbolAddress((void**)&z,     g_z);

    const dim3 blk(256);
    const float scale = 0.125f;  // 1/sqrt(64)

    // feat0 = inorm(x @ reduce_w^T + b);  feat = feat0
    gemm_tn<0><<<dim3(D_ / 64, B_ / 64, 1), blk>>>(x, reduce_w, reduce_b, nullptr, buf1,
                                                   DIN_, DIN_, DIN_, D_, 0, 0, 0, 1.f);
    rownorm<D_, false, false><<<B_, 128>>>(buf1, nullptr, nullptr, nullptr, feat0, feat);

    for (int l = 0; l < L_; l++) {
        // qkv = feat @ in_w^T + in_b
        gemm_tn<0><<<dim3(3 * D_ / 64, B_ / 64, 1), blk>>>(
            feat, in_w + (size_t)l * 3 * D_ * D_, in_b + l * 3 * D_, nullptr, qkv,
            D_, D_, D_, 3 * D_, 0, 0, 0, 1.f);
        // scores[h] = scale * q_h @ k_h^T   (batched over heads)
        gemm_tn<0><<<dim3(B_ / 64, B_ / 64, H_), blk>>>(
            qkv, qkv + D_, nullptr, nullptr, scores,
            HD_, 3 * D_, 3 * D_, B_, HD_, HD_, (long)B_ * B_, scale);
        softmax2048<<<H_ * B_, 256>>>(scores);
        // ctx[h] = attn[h] @ v_h   -> buf2[i, h*64+d]
        gemm_nn<<<dim3(1, B_ / 64, H_), blk>>>(
            scores, qkv + 2 * D_, buf2,
            B_, B_, 3 * D_, D_, (long)B_ * B_, (long)HD_, (long)HD_);
        // attn_out + residual -> buf1 ; LN1 -> feat
        gemm_tn<2><<<dim3(D_ / 64, B_ / 64, 1), blk>>>(
            buf2, out_w + (size_t)l * D_ * D_, out_b + l * D_, feat, buf1,
            D_, D_, D_, D_, 0, 0, 0, 1.f);
        rownorm<D_, true, false><<<B_, 128>>>(buf1, nullptr, ln1_w + l * D_, ln1_b + l * D_, feat, nullptr);
        // FFN
        gemm_tn<1><<<dim3(D_ / 64, B_ / 64, 1), blk>>>(
            feat, ff1_w + (size_t)l * D_ * D_, ff1_b + l * D_, nullptr, buf2,
            D_, D_, D_, D_, 0, 0, 0, 1.f);
        gemm_tn<2><<<dim3(D_ / 64, B_ / 64, 1), blk>>>(
            buf2, ff2_w + (size_t)l * D_ * D_, ff2_b + l * D_, feat, buf1,
            D_, D_, D_, D_, 0, 0, 0, 1.f);
        rownorm<D_, true, false><<<B_, 128>>>(buf1, nullptr, ln2_w + l * D_, ln2_b + l * D_, feat, nullptr);
    }

    // feat = feat0 + inorm(feat)  -> buf1
    rownorm<D_, false, true><<<B_, 128>>>(feat, feat0, nullptr, nullptr, buf1, nullptr);

    // MLP: 512 -> 512 -> 512 -> 128
    gemm_tn<1><<<dim3(D_ / 64, B_ / 64, 1), blk>>>(buf1, mlp_w1, mlp_b1, nullptr, buf2,
                                                   D_, D_, D_, D_, 0, 0, 0, 1.f);
    gemm_tn<1><<<dim3(D_ / 64, B_ / 64, 1), blk>>>(buf2, mlp_w2, mlp_b2, nullptr, buf1,
                                                   D_, D_, D_, D_, 0, 0, 0, 1.f);
    gemm_tn<0><<<dim3(Q_ / 64, B_ / 64, 1), blk>>>(buf1, mlp_w3, mlp_b3, nullptr, buf2,
                                                   D_, D_, D_, Q_, 0, 0, 0, 1.f);
    rownorm<Q_, false, false><<<B_, 128>>>(buf2, nullptr, nullptr, nullptr, z, nullptr);

    cdist_logits<<<B_, 128>>>(z, highlights, negatives, out);
}

// round 2
// speedup vs baseline: 1.3271x; 1.3271x over previous
#include <cuda_runtime.h>
#include <math.h>

#define B_   2048
#define DIN_ 768
#define D_   512
#define H_   8
#define HD_  64
#define L_   3
#define P_   40
#define Q_   128
#define EPSF 1e-5f

typedef unsigned long long ull;

// ---------------- scratch (device globals; no allocation allowed) ----------------
__device__ float g_feat0[B_ * D_];
__device__ float g_feat [B_ * D_];
__device__ float g_buf1 [B_ * D_];
__device__ float g_buf2 [B_ * D_];
__device__ float g_qkv  [B_ * 3 * D_];
__device__ float g_scores[(size_t)H_ * B_ * B_];   // 134 MB
__device__ float g_part [4 * B_ * D_];             // split-K partials, 16 MB
__device__ float g_z    [B_ * Q_];

// ---------------- packed f32x2 helpers ----------------
__device__ __forceinline__ ull bcast2(float x) {
    ull r; asm("mov.b64 %0, {%1, %1};" : "=l"(r) : "f"(x)); return r;
}
__device__ __forceinline__ void ffma2(ull& d, ull a, ull b) {
    asm("fma.rn.f32x2 %0, %1, %2, %3;" : "=l"(d) : "l"(a), "l"(b), "l"(d));
}
__device__ __forceinline__ float2 unpack2(ull v) {
    float2 r; asm("mov.b64 {%0, %1}, %2;" : "=f"(r.x), "=f"(r.y) : "l"(v)); return r;
}
union F4U { float4 f; ull u[2]; };

// ================= GEMM TN: C = alpha*(A @ W^T) [+bias][+relu][+res] =================
// A:[M,K] lda, W:[N,K] ldw, C:[M,N] ldc. BM=128 fixed. TM=8.
// BN=128 -> TN=8 (256 thr); BN=64 -> TN=4 (256 thr).
// EPI: 0 = alpha+bias(opt), 1 = bias+relu, 2 = bias+residual
template<int BN, int TN, int EPI>
__global__ __launch_bounds__(256)
void gemm_tn_f2(const float* __restrict__ A, const float* __restrict__ W,
                const float* __restrict__ bias, const float* __restrict__ res,
                float* __restrict__ C, int K, int lda, int ldw, int ldc,
                long sA, long sW, long sC, float alpha)
{
    A += (long)blockIdx.z * sA;
    W += (long)blockIdx.z * sW;
    C += (long)blockIdx.z * sC;
    __shared__ float As[8][128];
    __shared__ float Ws[8][BN];
    const int tid = threadIdx.x;
    const int tx = tid & 15;        // 16 column groups
    const int ty = tid >> 4;        // 16 row groups (TM=8)
    const int m0 = blockIdx.y * 128, n0 = blockIdx.x * BN;
    const int lrow = tid >> 1, lks = (tid & 1) << 2;
    const bool wact = (BN == 128) || (tid < 128);

    float4 ra = *(const float4*)&A[(size_t)(m0 + lrow) * lda + lks];
    float4 rw = {0,0,0,0};
    if (wact) rw = *(const float4*)&W[(size_t)(n0 + lrow) * ldw + lks];

    ull acc[8][TN / 2];
    #pragma unroll
    for (int i = 0; i < 8; i++)
        #pragma unroll
        for (int j = 0; j < TN / 2; j++) acc[i][j] = 0ull;

    for (int k0 = 0; k0 < K; k0 += 8) {
        As[lks + 0][lrow] = ra.x; As[lks + 1][lrow] = ra.y;
        As[lks + 2][lrow] = ra.z; As[lks + 3][lrow] = ra.w;
        if (wact) {
            Ws[lks + 0][lrow] = rw.x; Ws[lks + 1][lrow] = rw.y;
            Ws[lks + 2][lrow] = rw.z; Ws[lks + 3][lrow] = rw.w;
        }
        __syncthreads();
        if (k0 + 8 < K) {
            ra = *(const float4*)&A[(size_t)(m0 + lrow) * lda + k0 + 8 + lks];
            if (wact) rw = *(const float4*)&W[(size_t)(n0 + lrow) * ldw + k0 + 8 + lks];
        }
        #pragma unroll
        for (int kk = 0; kk < 8; kk++) {
            float4 a0 = *(const float4*)&As[kk][ty * 8];
            float4 a1 = *(const float4*)&As[kk][ty * 8 + 4];
            F4U b0; b0.f = *(const float4*)&Ws[kk][tx * TN];
            F4U b1;
            if (TN == 8) b1.f = *(const float4*)&Ws[kk][tx * TN + 4];
            float av[8] = {a0.x, a0.y, a0.z, a0.w, a1.x, a1.y, a1.z, a1.w};
            #pragma unroll
            for (int i = 0; i < 8; i++) {
                ull ab = bcast2(av[i]);
                ffma2(acc[i][0], ab, b0.u[0]);
                ffma2(acc[i][1], ab, b0.u[1]);
                if (TN == 8) {
                    ffma2(acc[i][2], ab, b1.u[0]);
                    ffma2(acc[i][3], ab, b1.u[1]);
                }
            }
        }
        __syncthreads();
    }

    #pragma unroll
    for (int i = 0; i < 8; i++) {
        const size_t ro = (size_t)(m0 + ty * 8 + i) * ldc;
        #pragma unroll
        for (int j2 = 0; j2 < TN / 2; j2++) {
            int n = n0 + tx * TN + 2 * j2;
            float2 v = unpack2(acc[i][j2]);
            v.x *= alpha; v.y *= alpha;
            if (bias) { v.x += bias[n]; v.y += bias[n + 1]; }
            if (EPI == 1) { v.x = fmaxf(v.x, 0.f); v.y = fmaxf(v.y, 0.f); }
            if (EPI == 2) { v.x += res[ro + n]; v.y += res[ro + n + 1]; }
            *(float2*)&C[ro + n] = v;
        }
    }
}

// ================= ctx GEMM (NN, split-K): part[s] += attn_h @ V_h =================
// grid (1, 16, 32): z = h*4 + s. A=scores[h] [2048,2048], B=V rows [2048,64] ldb=1536.
__global__ __launch_bounds__(256)
void ctx_gemm(const float* __restrict__ scores, const float* __restrict__ v,
              float* __restrict__ part)
{
    const int h = blockIdx.z >> 2, s = blockIdx.z & 3;
    const float* A  = scores + (size_t)h * B_ * B_;
    const float* Bm = v + h * HD_;
    const int m0 = blockIdx.y * 128;
    const int kS = s * 512;
    __shared__ float As[8][128];
    __shared__ float Bs[8][64];
    const int tid = threadIdx.x;
    const int tx = tid & 15, ty = tid >> 4;
    const int lrow = tid >> 1, lks = (tid & 1) << 2;
    const int bkk = tid >> 4, bnc = (tid & 15) << 2;   // for tid<128

    float4 ra = *(const float4*)&A[(size_t)(m0 + lrow) * 2048 + kS + lks];
    float4 rb = {0,0,0,0};
    if (tid < 128) rb = *(const float4*)&Bm[(size_t)(kS + bkk) * 1536 + bnc];

    ull acc[8][2];
    #pragma unroll
    for (int i = 0; i < 8; i++) { acc[i][0] = 0ull; acc[i][1] = 0ull; }

    for (int k0 = 0; k0 < 512; k0 += 8) {
        As[lks + 0][lrow] = ra.x; As[lks + 1][lrow] = ra.y;
        As[lks + 2][lrow] = ra.z; As[lks + 3][lrow] = ra.w;
        if (tid < 128) *(float4*)&Bs[bkk][bnc] = rb;
        __syncthreads();
        if (k0 + 8 < 512) {
            ra = *(const float4*)&A[(size_t)(m0 + lrow) * 2048 + kS + k0 + 8 + lks];
            if (tid < 128) rb = *(const float4*)&Bm[(size_t)(kS + k0 + 8 + bkk) * 1536 + bnc];
        }
        #pragma unroll
        for (int kk = 0; kk < 8; kk++) {
            float4 a0 = *(const float4*)&As[kk][ty * 8];
            float4 a1 = *(const float4*)&As[kk][ty * 8 + 4];
            F4U b0; b0.f = *(const float4*)&Bs[kk][tx * 4];
            float av[8] = {a0.x, a0.y, a0.z, a0.w, a1.x, a1.y, a1.z, a1.w};
            #pragma unroll
            for (int i = 0; i < 8; i++) {
                ull ab = bcast2(av[i]);
                ffma2(acc[i][0], ab, b0.u[0]);
                ffma2(acc[i][1], ab, b0.u[1]);
            }
        }
        __syncthreads();
    }

    float* C = part + (size_t)s * (B_ * D_) + h * HD_;
    #pragma unroll
    for (int i = 0; i < 8; i++) {
        const size_t ro = (size_t)(m0 + ty * 8 + i) * D_;
        #pragma unroll
        for (int j2 = 0; j2 < 2; j2++) {
            float2 v2 = unpack2(acc[i][j2]);
            *(float2*)&C[ro + tx * 4 + 2 * j2] = v2;
        }
    }
}

__global__ __launch_bounds__(256)
void reduce4(const float* __restrict__ part, float* __restrict__ out)
{
    const int i = blockIdx.x * 256 + threadIdx.x;    // float4 index
    const int N4 = B_ * D_ / 4;
    const float4* p = (const float4*)part;
    float4 a = p[i], b = p[i + N4], c = p[i + 2 * N4], d = p[i + 3 * N4];
    float4 r = {a.x + b.x + c.x + d.x, a.y + b.y + c.y + d.y,
                a.z + b.z + c.z + d.z, a.w + b.w + c.w + d.w};
    ((float4*)out)[i] = r;
}

// ---------------- softmax over rows of length 2048 (one block/row, float4) ----------------
__global__ __launch_bounds__(256)
void softmax2048(float* __restrict__ S)
{
    float4* row = (float4*)(S + (size_t)blockIdx.x * 2048);
    const int t = threadIdx.x;
    float4 v0 = row[t], v1 = row[t + 256];
    float mx = fmaxf(fmaxf(fmaxf(v0.x, v0.y), fmaxf(v0.z, v0.w)),
                     fmaxf(fmaxf(v1.x, v1.y), fmaxf(v1.z, v1.w)));
    __shared__ float sm[8];
    #pragma unroll
    for (int o = 16; o > 0; o >>= 1) mx = fmaxf(mx, __shfl_xor_sync(0xffffffffu, mx, o));
    if ((t & 31) == 0) sm[t >> 5] = mx;
    __syncthreads();
    mx = fmaxf(fmaxf(fmaxf(sm[0], sm[1]), fmaxf(sm[2], sm[3])),
               fmaxf(fmaxf(sm[4], sm[5]), fmaxf(sm[6], sm[7])));
    v0.x = __expf(v0.x - mx); v0.y = __expf(v0.y - mx);
    v0.z = __expf(v0.z - mx); v0.w = __expf(v0.w - mx);
    v1.x = __expf(v1.x - mx); v1.y = __expf(v1.y - mx);
    v1.z = __expf(v1.z - mx); v1.w = __expf(v1.w - mx);
    float s = v0.x + v0.y + v0.z + v0.w + v1.x + v1.y + v1.z + v1.w;
    __syncthreads();
    #pragma unroll
    for (int o = 16; o > 0; o >>= 1) s += __shfl_xor_sync(0xffffffffu, s, o);
    if ((t & 31) == 0) sm[t >> 5] = s;
    __syncthreads();
    s = sm[0] + sm[1] + sm[2] + sm[3] + sm[4] + sm[5] + sm[6] + sm[7];
    const float inv = 1.0f / s;
    v0.x *= inv; v0.y *= inv; v0.z *= inv; v0.w *= inv;
    v1.x *= inv; v1.y *= inv; v1.z *= inv; v1.w *= inv;
    row[t] = v0; row[t + 256] = v1;
}

// ---------------- per-row normalize (LN if AFFINE, InstanceNorm otherwise) ----------------
template<int N, bool AFFINE, bool ADD>
__global__ __launch_bounds__(128)
void rownorm(const float* __restrict__ src, const float* __restrict__ addv,
             const float* __restrict__ w, const float* __restrict__ bb,
             float* __restrict__ dst, float* __restrict__ dst2)
{
    constexpr int NPT = N / 128;
    const size_t base = (size_t)blockIdx.x * N;
    const int t = threadIdx.x;
    float v[NPT];
    float s = 0.f;
    #pragma unroll
    for (int i = 0; i < NPT; i++) { v[i] = src[base + t + i * 128]; s += v[i]; }
    __shared__ float sm[4];
    #pragma unroll
    for (int o = 16; o > 0; o >>= 1) s += __shfl_xor_sync(0xffffffffu, s, o);
    if ((t & 31) == 0) sm[t >> 5] = s;
    __syncthreads();
    s = sm[0] + sm[1] + sm[2] + sm[3];
    const float mean = s * (1.0f / N);
    float q = 0.f;
    #pragma unroll
    for (int i = 0; i < NPT; i++) { float d = v[i] - mean; q += d * d; }
    __syncthreads();
    #pragma unroll
    for (int o = 16; o > 0; o >>= 1) q += __shfl_xor_sync(0xffffffffu, q, o);
    if ((t & 31) == 0) sm[t >> 5] = q;
    __syncthreads();
    q = sm[0] + sm[1] + sm[2] + sm[3];
    const float r = rsqrtf(q * (1.0f / N) + EPSF);
    #pragma unroll
    for (int i = 0; i < NPT; i++) {
        int c = t + i * 128;
        float y = (v[i] - mean) * r;
        if (AFFINE) y = y * w[c] + bb[c];
        if (ADD)    y += addv[base + c];
        dst[base + c] = y;
        if (dst2) dst2[base + c] = y;
    }
}

// ---------------- cdist to prototypes, min over P, logits ----------------
__global__ __launch_bounds__(128)
void cdist_logits(const float* __restrict__ z, const float* __restrict__ hi,
                  const float* __restrict__ neg, float* __restrict__ out)
{
    __shared__ float zr[Q_];
    __shared__ float dist[128];
    const int b = blockIdx.x, t = threadIdx.x;
    zr[t] = z[(size_t)b * Q_ + t];
    dist[t] = 3.4e38f;
    __syncthreads();
    if (t < P_) {
        const float* p = hi + (size_t)t * Q_;
        float s = 0.f;
        #pragma unroll 8
        for (int d = 0; d < Q_; d++) { float df = zr[d] - p[d]; s = fmaf(df, df, s); }
        dist[t] = sqrtf(s);
    } else if (t >= 64 && t < 64 + P_) {
        const float* p = neg + (size_t)(t - 64) * Q_;
        float s = 0.f;
        #pragma unroll 8
        for (int d = 0; d < Q_; d++) { float df = zr[d] - p[d]; s = fmaf(df, df, s); }
        dist[t] = sqrtf(s);
    }
    __syncthreads();
    if (t == 0) {
        float m = 3.4e38f;
        for (int i = 0; i < P_; i++) m = fminf(m, dist[i]);
        out[b * 2 + 1] = -m;      // -positive_dist
    }
    if (t == 32) {
        float m = 3.4e38f;
        for (int i = 0; i < P_; i++) m = fminf(m, dist[64 + i]);
        out[b * 2 + 0] = -m;      // -negative_dist
    }
}

// ---------------- host driver ----------------
extern "C" void kernel_launch(void* const* d_in, const int* in_sizes, int n_in,
                              void* d_out, int out_size)
{
    const float* x        = (const float*)d_in[0];
    const float* reduce_w = (const float*)d_in[1];
    const float* reduce_b = (const float*)d_in[2];
    const float* in_w     = (const float*)d_in[3];
    const float* in_b     = (const float*)d_in[4];
    const float* out_w    = (const float*)d_in[5];
    const float* out_b    = (const float*)d_in[6];
    const float* ff1_w    = (const float*)d_in[7];
    const float* ff1_b    = (const float*)d_in[8];
    const float* ff2_w    = (const float*)d_in[9];
    const float* ff2_b    = (const float*)d_in[10];
    const float* ln1_w    = (const float*)d_in[11];
    const float* ln1_b    = (const float*)d_in[12];
    const float* ln2_w    = (const float*)d_in[13];
    const float* ln2_b    = (const float*)d_in[14];
    const float* mlp_w1   = (const float*)d_in[15];
    const float* mlp_b1   = (const float*)d_in[16];
    const float* mlp_w2   = (const float*)d_in[17];
    const float* mlp_b2   = (const float*)d_in[18];
    const float* mlp_w3   = (const float*)d_in[19];
    const float* mlp_b3   = (const float*)d_in[20];
    const float* highlights = (const float*)d_in[21];
    const float* negatives  = (const float*)d_in[22];
    float* out = (float*)d_out;

    float *feat0, *feat, *buf1, *buf2, *qkv, *scores, *part, *z;
    cudaGetSymbolAddress((void**)&feat0, g_feat0);
    cudaGetSymbolAddress((void**)&feat,  g_feat);
    cudaGetSymbolAddress((void**)&buf1,  g_buf1);
    cudaGetSymbolAddress((void**)&buf2,  g_buf2);
    cudaGetSymbolAddress((void**)&qkv,   g_qkv);
    cudaGetSymbolAddress((void**)&scores,g_scores);
    cudaGetSymbolAddress((void**)&part,  g_part);
    cudaGetSymbolAddress((void**)&z,     g_z);

    const dim3 blk(256);
    const float scale = 0.125f;  // 1/sqrt(64)

    // feat0 = inorm(x @ reduce_w^T + b);  feat = feat0
    gemm_tn_f2<64, 4, 0><<<dim3(D_ / 64, B_ / 128, 1), blk>>>(
        x, reduce_w, reduce_b, nullptr, buf1, DIN_, DIN_, DIN_, D_, 0, 0, 0, 1.f);
    rownorm<D_, false, false><<<B_, 128>>>(buf1, nullptr, nullptr, nullptr, feat0, feat);

    for (int l = 0; l < L_; l++) {
        // qkv = feat @ in_w^T + in_b
        gemm_tn_f2<128, 8, 0><<<dim3(3 * D_ / 128, B_ / 128, 1), blk>>>(
            feat, in_w + (size_t)l * 3 * D_ * D_, in_b + l * 3 * D_, nullptr, qkv,
            D_, D_, D_, 3 * D_, 0, 0, 0, 1.f);
        // scores[h] = scale * q_h @ k_h^T   (batched over heads)
        gemm_tn_f2<128, 8, 0><<<dim3(B_ / 128, B_ / 128, H_), blk>>>(
            qkv, qkv + D_, nullptr, nullptr, scores,
            HD_, 3 * D_, 3 * D_, B_, HD_, HD_, (long)B_ * B_, scale);
        softmax2048<<<H_ * B_, 256>>>(scores);
        // ctx: split-K over 4 chunks into partials, then reduce into buf2
        ctx_gemm<<<dim3(1, B_ / 128, H_ * 4), blk>>>(scores, qkv + 2 * D_, part);
        reduce4<<<B_ * D_ / 4 / 256, 256>>>(part, buf2);
        // attn_out + residual -> buf1 ; LN1 -> feat
        gemm_tn_f2<64, 4, 2><<<dim3(D_ / 64, B_ / 128, 1), blk>>>(
            buf2, out_w + (size_t)l * D_ * D_, out_b + l * D_, feat, buf1,
            D_, D_, D_, D_, 0, 0, 0, 1.f);
        rownorm<D_, true, false><<<B_, 128>>>(buf1, nullptr, ln1_w + l * D_, ln1_b + l * D_, feat, nullptr);
        // FFN
        gemm_tn_f2<64, 4, 1><<<dim3(D_ / 64, B_ / 128, 1), blk>>>(
            feat, ff1_w + (size_t)l * D_ * D_, ff1_b + l * D_, nullptr, buf2,
            D_, D_, D_, D_, 0, 0, 0, 1.f);
        gemm_tn_f2<64, 4, 2><<<dim3(D_ / 64, B_ / 128, 1), blk>>>(
            buf2, ff2_w + (size_t)l * D_ * D_, ff2_b + l * D_, feat, buf1,
            D_, D_, D_, D_, 0, 0, 0, 1.f);
        rownorm<D_, true, false><<<B_, 128>>>(buf1, nullptr, ln2_w + l * D_, ln2_b + l * D_, feat, nullptr);
    }

    // feat = feat0 + inorm(feat)  -> buf1
    rownorm<D_, false, true><<<B_, 128>>>(feat, feat0, nullptr, nullptr, buf1, nullptr);

    // MLP: 512 -> 512 -> 512 -> 128
    gemm_tn_f2<64, 4, 1><<<dim3(D_ / 64, B_ / 128, 1), blk>>>(
        buf1, mlp_w1, mlp_b1, nullptr, buf2, D_, D_, D_, D_, 0, 0, 0, 1.f);
    gemm_tn_f2<64, 4, 1><<<dim3(D_ / 64, B_ / 128, 1), blk>>>(
        buf2, mlp_w2, mlp_b2, nullptr, buf1, D_, D_, D_, D_, 0, 0, 0, 1.f);
    gemm_tn_f2<64, 4, 0><<<dim3(Q_ / 64, B_ / 128, 1), blk>>>(
        buf1, mlp_w3, mlp_b3, nullptr, buf2, D_, D_, D_, Q_, 0, 0, 0, 1.f);
    rownorm<Q_, false, false><<<B_, 128>>>(buf2, nullptr, nullptr, nullptr, z, nullptr);

    cdist_logits<<<B_, 128>>>(z, highlights, negatives, out);
}

// round 3
// speedup vs baseline: 1.9170x; 1.4444x over previous
#include <cuda_runtime.h>
#include <math.h>

#define B_   2048
#define DIN_ 768
#define D_   512
#define H_   8
#define HD_  64
#define L_   3
#define P_   40
#define Q_   128
#define EPSF 1e-5f

// ---------------- scratch (device globals; no allocation allowed) ----------------
__device__ float g_feat0[B_ * D_];
__device__ float g_feat [B_ * D_];
__device__ float g_buf1 [B_ * D_];
__device__ float g_buf2 [B_ * D_];
__device__ float g_qkv  [B_ * 3 * D_];
__device__ float g_scores[(size_t)H_ * B_ * B_];   // 134 MB
__device__ float g_part [4 * B_ * D_];             // split-K partials
__device__ float g_z    [B_ * Q_];

// ---------------- helpers ----------------
__device__ __forceinline__ float to_tf32(float x) {
    float r; asm("cvt.rna.tf32.f32 %0, %1;" : "=f"(r) : "f"(x)); return r;
}
__device__ __forceinline__ void mma_tf32(float* c, unsigned a0, unsigned a1,
                                         unsigned a2, unsigned a3,
                                         unsigned b0, unsigned b1) {
    asm volatile(
        "mma.sync.aligned.m16n8k8.row.col.f32.tf32.tf32.f32 "
        "{%0,%1,%2,%3}, {%4,%5,%6,%7}, {%8,%9}, {%0,%1,%2,%3};"
        : "+f"(c[0]), "+f"(c[1]), "+f"(c[2]), "+f"(c[3])
        : "r"(a0), "r"(a1), "r"(a2), "r"(a3), "r"(b0), "r"(b1));
}
__device__ __forceinline__ constexpr int permk(int k) { return (k & 3) * 4 + (k >> 2); }

#define AS_RS 20   // row stride (floats) for perm-K tiles; 80B keeps 16B alignment

// ================= tf32 MMA GEMM, TN: C = alpha*(A @ W^T) [+bias][+relu][+res] ========
// A:[M,K] lda, W:[N,K] ldw, C:[M,N] ldc. BM=128, BK=16. BN in {128, 64}.
// EPI: 0 = alpha+bias(opt), 1 = bias+relu, 2 = bias+residual
template<int BN, int EPI>
__global__ __launch_bounds__(256)
void gemm_mma_tn(const float* __restrict__ A, const float* __restrict__ W,
                 const float* __restrict__ bias, const float* __restrict__ res,
                 float* __restrict__ C, int K, int lda, int ldw, int ldc,
                 long sA, long sW, long sC, float alpha)
{
    constexpr int NT = BN / 16;       // n-tiles per warp
    A += (long)blockIdx.z * sA;
    W += (long)blockIdx.z * sW;
    C += (long)blockIdx.z * sC;
    __shared__ float As[128][AS_RS];
    __shared__ float Ws[BN][AS_RS];

    const int tid = threadIdx.x;
    const int w = tid >> 5, l = tid & 31, g = l >> 2, t = l & 3;
    const int wm = (w >> 1) * 32, wn = (w & 1) * (BN / 2);
    const int m0 = blockIdx.y * 128, n0 = blockIdx.x * BN;
    const int srow = tid >> 1, skb = (tid & 1) * 8;
    const bool wact = (BN == 128) || (tid < 128);

    float4 ra0 = *(const float4*)&A[(size_t)(m0 + srow) * lda + skb];
    float4 ra1 = *(const float4*)&A[(size_t)(m0 + srow) * lda + skb + 4];
    float4 rw0 = {0,0,0,0}, rw1 = {0,0,0,0};
    if (wact) {
        rw0 = *(const float4*)&W[(size_t)(n0 + srow) * ldw + skb];
        rw1 = *(const float4*)&W[(size_t)(n0 + srow) * ldw + skb + 4];
    }

    float acc[2][NT][4];
    #pragma unroll
    for (int mt = 0; mt < 2; mt++)
        #pragma unroll
        for (int nt = 0; nt < NT; nt++)
            #pragma unroll
            for (int i = 0; i < 4; i++) acc[mt][nt][i] = 0.f;

    for (int k0 = 0; k0 < K; k0 += 16) {
        {
            float va[8] = {ra0.x, ra0.y, ra0.z, ra0.w, ra1.x, ra1.y, ra1.z, ra1.w};
            #pragma unroll
            for (int i = 0; i < 8; i++) As[srow][permk(skb + i)] = to_tf32(va[i]);
            if (wact) {
                float vw[8] = {rw0.x, rw0.y, rw0.z, rw0.w, rw1.x, rw1.y, rw1.z, rw1.w};
                #pragma unroll
                for (int i = 0; i < 8; i++) Ws[srow][permk(skb + i)] = to_tf32(vw[i]);
            }
        }
        __syncthreads();
        if (k0 + 16 < K) {
            ra0 = *(const float4*)&A[(size_t)(m0 + srow) * lda + k0 + 16 + skb];
            ra1 = *(const float4*)&A[(size_t)(m0 + srow) * lda + k0 + 16 + skb + 4];
            if (wact) {
                rw0 = *(const float4*)&W[(size_t)(n0 + srow) * ldw + k0 + 16 + skb];
                rw1 = *(const float4*)&W[(size_t)(n0 + srow) * ldw + k0 + 16 + skb + 4];
            }
        }
        uint4 Af[4];
        Af[0] = *(const uint4*)&As[wm + g     ][4 * t];
        Af[1] = *(const uint4*)&As[wm + g + 8 ][4 * t];
        Af[2] = *(const uint4*)&As[wm + g + 16][4 * t];
        Af[3] = *(const uint4*)&As[wm + g + 24][4 * t];
        #pragma unroll
        for (int nt = 0; nt < NT; nt++) {
            uint4 Bf = *(const uint4*)&Ws[wn + 8 * nt + g][4 * t];
            // k-step 0: components .x/.y ; k-step 1: .z/.w
            mma_tf32(acc[0][nt], Af[0].x, Af[1].x, Af[0].y, Af[1].y, Bf.x, Bf.y);
            mma_tf32(acc[1][nt], Af[2].x, Af[3].x, Af[2].y, Af[3].y, Bf.x, Bf.y);
            mma_tf32(acc[0][nt], Af[0].z, Af[1].z, Af[0].w, Af[1].w, Bf.z, Bf.w);
            mma_tf32(acc[1][nt], Af[2].z, Af[3].z, Af[2].w, Af[3].w, Bf.z, Bf.w);
        }
        __syncthreads();
    }

    #pragma unroll
    for (int mt = 0; mt < 2; mt++) {
        const int r0 = m0 + wm + 16 * mt + g;
        #pragma unroll
        for (int nt = 0; nt < NT; nt++) {
            const int n = n0 + wn + 8 * nt + 2 * t;
            #pragma unroll
            for (int half = 0; half < 2; half++) {
                const int r = r0 + 8 * half;
                const size_t ro = (size_t)r * ldc;
                float2 v = { acc[mt][nt][2 * half], acc[mt][nt][2 * half + 1] };
                v.x *= alpha; v.y *= alpha;
                if (bias) { v.x += bias[n]; v.y += bias[n + 1]; }
                if (EPI == 1) { v.x = fmaxf(v.x, 0.f); v.y = fmaxf(v.y, 0.f); }
                if (EPI == 2) { v.x += res[ro + n]; v.y += res[ro + n + 1]; }
                *(float2*)&C[ro + n] = v;
            }
        }
    }
}

// ================= ctx GEMM (NN, tf32 MMA, split-K=4): part[s] = attn_h @ V_h ==========
// grid (1, 16, 32): z = h*4 + s. A = scores[h] [2048,2048]; V rows [2048,64] ldb=1536.
__global__ __launch_bounds__(256)
void ctx_mma(const float* __restrict__ scores, const float* __restrict__ v,
             float* __restrict__ part)
{
    constexpr int BN = 64, NT = 4;
    const int h = blockIdx.z >> 2, s = blockIdx.z & 3;
    const float* A  = scores + (size_t)h * B_ * B_;
    const float* Bm = v + h * HD_;
    const int m0 = blockIdx.y * 128;
    const int kS = s * 512;

    __shared__ float As[128][AS_RS];
    __shared__ float Bs[16][BN + 4];

    const int tid = threadIdx.x;
    const int w = tid >> 5, l = tid & 31, g = l >> 2, t = l & 3;
    const int wm = (w >> 1) * 32, wn = (w & 1) * 32;
    const int srow = tid >> 1, skb = (tid & 1) * 8;
    const int bk = tid >> 4, bn = (tid & 15) * 4;

    float4 ra0 = *(const float4*)&A[(size_t)(m0 + srow) * 2048 + kS + skb];
    float4 ra1 = *(const float4*)&A[(size_t)(m0 + srow) * 2048 + kS + skb + 4];
    float4 rb  = *(const float4*)&Bm[(size_t)(kS + bk) * 1536 + bn];

    float acc[2][NT][4];
    #pragma unroll
    for (int mt = 0; mt < 2; mt++)
        #pragma unroll
        for (int nt = 0; nt < NT; nt++)
            #pragma unroll
            for (int i = 0; i < 4; i++) acc[mt][nt][i] = 0.f;

    for (int k0 = 0; k0 < 512; k0 += 16) {
        {
            float va[8] = {ra0.x, ra0.y, ra0.z, ra0.w, ra1.x, ra1.y, ra1.z, ra1.w};
            #pragma unroll
            for (int i = 0; i < 8; i++) As[srow][permk(skb + i)] = to_tf32(va[i]);
            Bs[bk][bn + 0] = to_tf32(rb.x); Bs[bk][bn + 1] = to_tf32(rb.y);
            Bs[bk][bn + 2] = to_tf32(rb.z); Bs[bk][bn + 3] = to_tf32(rb.w);
        }
        __syncthreads();
        if (k0 + 16 < 512) {
            ra0 = *(const float4*)&A[(size_t)(m0 + srow) * 2048 + kS + k0 + 16 + skb];
            ra1 = *(const float4*)&A[(size_t)(m0 + srow) * 2048 + kS + k0 + 16 + skb + 4];
            rb  = *(const float4*)&Bm[(size_t)(kS + k0 + 16 + bk) * 1536 + bn];
        }
        uint4 Af[4];
        Af[0] = *(const uint4*)&As[wm + g     ][4 * t];
        Af[1] = *(const uint4*)&As[wm + g + 8 ][4 * t];
        Af[2] = *(const uint4*)&As[wm + g + 16][4 * t];
        Af[3] = *(const uint4*)&As[wm + g + 24][4 * t];
        #pragma unroll
        for (int nt = 0; nt < NT; nt++) {
            const int nc = wn + 8 * nt + g;
            unsigned b00 = __float_as_uint(Bs[t    ][nc]);
            unsigned b10 = __float_as_uint(Bs[t + 4][nc]);
            unsigned b01 = __float_as_uint(Bs[t + 8][nc]);
            unsigned b11 = __float_as_uint(Bs[t + 12][nc]);
            mma_tf32(acc[0][nt], Af[0].x, Af[1].x, Af[0].y, Af[1].y, b00, b10);
            mma_tf32(acc[1][nt], Af[2].x, Af[3].x, Af[2].y, Af[3].y, b00, b10);
            mma_tf32(acc[0][nt], Af[0].z, Af[1].z, Af[0].w, Af[1].w, b01, b11);
            mma_tf32(acc[1][nt], Af[2].z, Af[3].z, Af[2].w, Af[3].w, b01, b11);
        }
        __syncthreads();
    }

    float* C = part + (size_t)s * (B_ * D_) + h * HD_;
    #pragma unroll
    for (int mt = 0; mt < 2; mt++) {
        const int r0 = m0 + wm + 16 * mt + g;
        #pragma unroll
        for (int nt = 0; nt < NT; nt++) {
            const int n = wn + 8 * nt + 2 * t;
            #pragma unroll
            for (int half = 0; half < 2; half++) {
                const size_t ro = (size_t)(r0 + 8 * half) * D_;
                float2 v2 = { acc[mt][nt][2 * half], acc[mt][nt][2 * half + 1] };
                *(float2*)&C[ro + n] = v2;
            }
        }
    }
}

__global__ __launch_bounds__(256)
void reduce4(const float* __restrict__ part, float* __restrict__ out)
{
    const int i = blockIdx.x * 256 + threadIdx.x;    // float4 index
    const int N4 = B_ * D_ / 4;
    const float4* p = (const float4*)part;
    float4 a = p[i], b = p[i + N4], c = p[i + 2 * N4], d = p[i + 3 * N4];
    float4 r = {a.x + b.x + c.x + d.x, a.y + b.y + c.y + d.y,
                a.z + b.z + c.z + d.z, a.w + b.w + c.w + d.w};
    ((float4*)out)[i] = r;
}

// ---------------- softmax over rows of length 2048 (one block/row, float4) ----------------
__global__ __launch_bounds__(256)
void softmax2048(float* __restrict__ S)
{
    float4* row = (float4*)(S + (size_t)blockIdx.x * 2048);
    const int t = threadIdx.x;
    float4 v0 = row[t], v1 = row[t + 256];
    float mx = fmaxf(fmaxf(fmaxf(v0.x, v0.y), fmaxf(v0.z, v0.w)),
                     fmaxf(fmaxf(v1.x, v1.y), fmaxf(v1.z, v1.w)));
    __shared__ float sm[8];
    #pragma unroll
    for (int o = 16; o > 0; o >>= 1) mx = fmaxf(mx, __shfl_xor_sync(0xffffffffu, mx, o));
    if ((t & 31) == 0) sm[t >> 5] = mx;
    __syncthreads();
    mx = fmaxf(fmaxf(fmaxf(sm[0], sm[1]), fmaxf(sm[2], sm[3])),
               fmaxf(fmaxf(sm[4], sm[5]), fmaxf(sm[6], sm[7])));
    v0.x = __expf(v0.x - mx); v0.y = __expf(v0.y - mx);
    v0.z = __expf(v0.z - mx); v0.w = __expf(v0.w - mx);
    v1.x = __expf(v1.x - mx); v1.y = __expf(v1.y - mx);
    v1.z = __expf(v1.z - mx); v1.w = __expf(v1.w - mx);
    float s = v0.x + v0.y + v0.z + v0.w + v1.x + v1.y + v1.z + v1.w;
    __syncthreads();
    #pragma unroll
    for (int o = 16; o > 0; o >>= 1) s += __shfl_xor_sync(0xffffffffu, s, o);
    if ((t & 31) == 0) sm[t >> 5] = s;
    __syncthreads();
    s = sm[0] + sm[1] + sm[2] + sm[3] + sm[4] + sm[5] + sm[6] + sm[7];
    const float inv = 1.0f / s;
    v0.x *= inv; v0.y *= inv; v0.z *= inv; v0.w *= inv;
    v1.x *= inv; v1.y *= inv; v1.z *= inv; v1.w *= inv;
    row[t] = v0; row[t + 256] = v1;
}

// ---------------- per-row normalize (LN if AFFINE, InstanceNorm otherwise) ----------------
template<int N, bool AFFINE, bool ADD>
__global__ __launch_bounds__(128)
void rownorm(const float* __restrict__ src, const float* __restrict__ addv,
             const float* __restrict__ w, const float* __restrict__ bb,
             float* __restrict__ dst, float* __restrict__ dst2)
{
    constexpr int NPT = N / 128;
    const size_t base = (size_t)blockIdx.x * N;
    const int t = threadIdx.x;
    float v[NPT];
    float s = 0.f;
    #pragma unroll
    for (int i = 0; i < NPT; i++) { v[i] = src[base + t + i * 128]; s += v[i]; }
    __shared__ float sm[4];
    #pragma unroll
    for (int o = 16; o > 0; o >>= 1) s += __shfl_xor_sync(0xffffffffu, s, o);
    if ((t & 31) == 0) sm[t >> 5] = s;
    __syncthreads();
    s = sm[0] + sm[1] + sm[2] + sm[3];
    const float mean = s * (1.0f / N);
    float q = 0.f;
    #pragma unroll
    for (int i = 0; i < NPT; i++) { float d = v[i] - mean; q += d * d; }
    __syncthreads();
    #pragma unroll
    for (int o = 16; o > 0; o >>= 1) q += __shfl_xor_sync(0xffffffffu, q, o);
    if ((t & 31) == 0) sm[t >> 5] = q;
    __syncthreads();
    q = sm[0] + sm[1] + sm[2] + sm[3];
    const float r = rsqrtf(q * (1.0f / N) + EPSF);
    #pragma unroll
    for (int i = 0; i < NPT; i++) {
        int c = t + i * 128;
        float y = (v[i] - mean) * r;
        if (AFFINE) y = y * w[c] + bb[c];
        if (ADD)    y += addv[base + c];
        dst[base + c] = y;
        if (dst2) dst2[base + c] = y;
    }
}

// ---------------- cdist to prototypes, min over P, logits ----------------
__global__ __launch_bounds__(128)
void cdist_logits(const float* __restrict__ z, const float* __restrict__ hi,
                  const float* __restrict__ neg, float* __restrict__ out)
{
    __shared__ float zr[Q_];
    __shared__ float dist[128];
    const int b = blockIdx.x, t = threadIdx.x;
    zr[t] = z[(size_t)b * Q_ + t];
    dist[t] = 3.4e38f;
    __syncthreads();
    if (t < P_) {
        const float* p = hi + (size_t)t * Q_;
        float s = 0.f;
        #pragma unroll 8
        for (int d = 0; d < Q_; d++) { float df = zr[d] - p[d]; s = fmaf(df, df, s); }
        dist[t] = sqrtf(s);
    } else if (t >= 64 && t < 64 + P_) {
        const float* p = neg + (size_t)(t - 64) * Q_;
        float s = 0.f;
        #pragma unroll 8
        for (int d = 0; d < Q_; d++) { float df = zr[d] - p[d]; s = fmaf(df, df, s); }
        dist[t] = sqrtf(s);
    }
    __syncthreads();
    if (t == 0) {
        float m = 3.4e38f;
        for (int i = 0; i < P_; i++) m = fminf(m, dist[i]);
        out[b * 2 + 1] = -m;      // -positive_dist
    }
    if (t == 32) {
        float m = 3.4e38f;
        for (int i = 0; i < P_; i++) m = fminf(m, dist[64 + i]);
        out[b * 2 + 0] = -m;      // -negative_dist
    }
}

// ---------------- host driver ----------------
extern "C" void kernel_launch(void* const* d_in, const int* in_sizes, int n_in,
                              void* d_out, int out_size)
{
    const float* x        = (const float*)d_in[0];
    const float* reduce_w = (const float*)d_in[1];
    const float* reduce_b = (const float*)d_in[2];
    const float* in_w     = (const float*)d_in[3];
    const float* in_b     = (const float*)d_in[4];
    const float* out_w    = (const float*)d_in[5];
    const float* out_b    = (const float*)d_in[6];
    const float* ff1_w    = (const float*)d_in[7];
    const float* ff1_b    = (const float*)d_in[8];
    const float* ff2_w    = (const float*)d_in[9];
    const float* ff2_b    = (const float*)d_in[10];
    const float* ln1_w    = (const float*)d_in[11];
    const float* ln1_b    = (const float*)d_in[12];
    const float* ln2_w    = (const float*)d_in[13];
    const float* ln2_b    = (const float*)d_in[14];
    const float* mlp_w1   = (const float*)d_in[15];
    const float* mlp_b1   = (const float*)d_in[16];
    const float* mlp_w2   = (const float*)d_in[17];
    const float* mlp_b2   = (const float*)d_in[18];
    const float* mlp_w3   = (const float*)d_in[19];
    const float* mlp_b3   = (const float*)d_in[20];
    const float* highlights = (const float*)d_in[21];
    const float* negatives  = (const float*)d_in[22];
    float* out = (float*)d_out;

    float *feat0, *feat, *buf1, *buf2, *qkv, *scores, *part, *z;
    cudaGetSymbolAddress((void**)&feat0, g_feat0);
    cudaGetSymbolAddress((void**)&feat,  g_feat);
    cudaGetSymbolAddress((void**)&buf1,  g_buf1);
    cudaGetSymbolAddress((void**)&buf2,  g_buf2);
    cudaGetSymbolAddress((void**)&qkv,   g_qkv);
    cudaGetSymbolAddress((void**)&scores,g_scores);
    cudaGetSymbolAddress((void**)&part,  g_part);
    cudaGetSymbolAddress((void**)&z,     g_z);

    const dim3 blk(256);
    const float scale = 0.125f;  // 1/sqrt(64)

    // feat0 = inorm(x @ reduce_w^T + b);  feat = feat0
    gemm_mma_tn<128, 0><<<dim3(D_ / 128, B_ / 128, 1), blk>>>(
        x, reduce_w, reduce_b, nullptr, buf1, DIN_, DIN_, DIN_, D_, 0, 0, 0, 1.f);
    rownorm<D_, false, false><<<B_, 128>>>(buf1, nullptr, nullptr, nullptr, feat0, feat);

    for (int l = 0; l < L_; l++) {
        // qkv = feat @ in_w^T + in_b
        gemm_mma_tn<128, 0><<<dim3(3 * D_ / 128, B_ / 128, 1), blk>>>(
            feat, in_w + (size_t)l * 3 * D_ * D_, in_b + l * 3 * D_, nullptr, qkv,
            D_, D_, D_, 3 * D_, 0, 0, 0, 1.f);
        // scores[h] = scale * q_h @ k_h^T   (batched over heads)
        gemm_mma_tn<128, 0><<<dim3(B_ / 128, B_ / 128, H_), blk>>>(
            qkv, qkv + D_, nullptr, nullptr, scores,
            HD_, 3 * D_, 3 * D_, B_, HD_, HD_, (long)B_ * B_, scale);
        softmax2048<<<H_ * B_, 256>>>(scores);
        // ctx: tf32 MMA split-K into partials, then reduce into buf2
        ctx_mma<<<dim3(1, B_ / 128, H_ * 4), blk>>>(scores, qkv + 2 * D_, part);
        reduce4<<<B_ * D_ / 4 / 256, 256>>>(part, buf2);
        // attn_out + residual -> buf1 ; LN1 -> feat
        gemm_mma_tn<128, 2><<<dim3(D_ / 128, B_ / 128, 1), blk>>>(
            buf2, out_w + (size_t)l * D_ * D_, out_b + l * D_, feat, buf1,
            D_, D_, D_, D_, 0, 0, 0, 1.f);
        rownorm<D_, true, false><<<B_, 128>>>(buf1, nullptr, ln1_w + l * D_, ln1_b + l * D_, feat, nullptr);
        // FFN
        gemm_mma_tn<128, 1><<<dim3(D_ / 128, B_ / 128, 1), blk>>>(
            feat, ff1_w + (size_t)l * D_ * D_, ff1_b + l * D_, nullptr, buf2,
            D_, D_, D_, D_, 0, 0, 0, 1.f);
        gemm_mma_tn<128, 2><<<dim3(D_ / 128, B_ / 128, 1), blk>>>(
            buf2, ff2_w + (size_t)l * D_ * D_, ff2_b + l * D_, feat, buf1,
            D_, D_, D_, D_, 0, 0, 0, 1.f);
        rownorm<D_, true, false><<<B_, 128>>>(buf1, nullptr, ln2_w + l * D_, ln2_b + l * D_, feat, nullptr);
    }

    // feat = feat0 + inorm(feat)  -> buf1
    rownorm<D_, false, true><<<B_, 128>>>(feat, feat0, nullptr, nullptr, buf1, nullptr);

    // MLP: 512 -> 512 -> 512 -> 128
    gemm_mma_tn<128, 1><<<dim3(D_ / 128, B_ / 128, 1), blk>>>(
        buf1, mlp_w1, mlp_b1, nullptr, buf2, D_, D_, D_, D_, 0, 0, 0, 1.f);
    gemm_mma_tn<128, 1><<<dim3(D_ / 128, B_ / 128, 1), blk>>>(
        buf2, mlp_w2, mlp_b2, nullptr, buf1, D_, D_, D_, D_, 0, 0, 0, 1.f);
    gemm_mma_tn<128, 0><<<dim3(Q_ / 128, B_ / 128, 1), blk>>>(
        buf1, mlp_w3, mlp_b3, nullptr, buf2, D_, D_, D_, Q_, 0, 0, 0, 1.f);
    rownorm<Q_, false, false><<<B_, 128>>>(buf2, nullptr, nullptr, nullptr, z, nullptr);

    cdist_logits<<<B_, 128>>>(z, highlights, negatives, out);
}

// round 4
// speedup vs baseline: 2.5924x; 1.3524x over previous
#include <cuda_runtime.h>
#include <math.h>

#define B_   2048
#define DIN_ 768
#define D_   512
#define H_   8
#define HD_  64
#define L_   3
#define P_   40
#define Q_   128
#define EPSF 1e-5f

// ---------------- scratch (device globals; no allocation allowed) ----------------
__device__ float g_feat0[B_ * D_];
__device__ float g_feat [B_ * D_];
__device__ float g_buf1 [B_ * D_];
__device__ float g_buf2 [B_ * D_];
__device__ float g_qkv  [B_ * 3 * D_];
__device__ float g_z    [B_ * Q_];

// ---------------- helpers ----------------
__device__ __forceinline__ float to_tf32(float x) {
    float r; asm("cvt.rna.tf32.f32 %0, %1;" : "=f"(r) : "f"(x)); return r;
}
__device__ __forceinline__ void mma_tf32(float* c, unsigned a0, unsigned a1,
                                         unsigned a2, unsigned a3,
                                         unsigned b0, unsigned b1) {
    asm volatile(
        "mma.sync.aligned.m16n8k8.row.col.f32.tf32.tf32.f32 "
        "{%0,%1,%2,%3}, {%4,%5,%6,%7}, {%8,%9}, {%0,%1,%2,%3};"
        : "+f"(c[0]), "+f"(c[1]), "+f"(c[2]), "+f"(c[3])
        : "r"(a0), "r"(a1), "r"(a2), "r"(a3), "r"(b0), "r"(b1));
}
__device__ __forceinline__ constexpr int permk(int k) { return (k & 3) * 4 + (k >> 2); }

#define AS_RS 20   // row stride (floats) for perm-K tiles in the dense GEMMs

// ================= tf32 MMA GEMM, TN: C = alpha*(A @ W^T) [+bias][+relu][+res] ========
template<int BN, int EPI>
__global__ __launch_bounds__(256)
void gemm_mma_tn(const float* __restrict__ A, const float* __restrict__ W,
                 const float* __restrict__ bias, const float* __restrict__ res,
                 float* __restrict__ C, int K, int lda, int ldw, int ldc,
                 long sA, long sW, long sC, float alpha)
{
    constexpr int NT = BN / 16;
    A += (long)blockIdx.z * sA;
    W += (long)blockIdx.z * sW;
    C += (long)blockIdx.z * sC;
    __shared__ float As[128][AS_RS];
    __shared__ float Ws[BN][AS_RS];

    const int tid = threadIdx.x;
    const int w = tid >> 5, lb = tid & 31, g = lb >> 2, t = lb & 3;
    const int wm = (w >> 1) * 32, wn = (w & 1) * (BN / 2);
    const int m0 = blockIdx.y * 128, n0 = blockIdx.x * BN;
    const int srow = tid >> 1, skb = (tid & 1) * 8;
    const bool wact = (BN == 128) || (tid < 128);

    float4 ra0 = *(const float4*)&A[(size_t)(m0 + srow) * lda + skb];
    float4 ra1 = *(const float4*)&A[(size_t)(m0 + srow) * lda + skb + 4];
    float4 rw0 = {0,0,0,0}, rw1 = {0,0,0,0};
    if (wact) {
        rw0 = *(const float4*)&W[(size_t)(n0 + srow) * ldw + skb];
        rw1 = *(const float4*)&W[(size_t)(n0 + srow) * ldw + skb + 4];
    }

    float acc[2][NT][4];
    #pragma unroll
    for (int mt = 0; mt < 2; mt++)
        #pragma unroll
        for (int nt = 0; nt < NT; nt++)
            #pragma unroll
            for (int i = 0; i < 4; i++) acc[mt][nt][i] = 0.f;

    for (int k0 = 0; k0 < K; k0 += 16) {
        {
            float va[8] = {ra0.x, ra0.y, ra0.z, ra0.w, ra1.x, ra1.y, ra1.z, ra1.w};
            #pragma unroll
            for (int i = 0; i < 8; i++) As[srow][permk(skb + i)] = to_tf32(va[i]);
            if (wact) {
                float vw[8] = {rw0.x, rw0.y, rw0.z, rw0.w, rw1.x, rw1.y, rw1.z, rw1.w};
                #pragma unroll
                for (int i = 0; i < 8; i++) Ws[srow][permk(skb + i)] = to_tf32(vw[i]);
            }
        }
        __syncthreads();
        if (k0 + 16 < K) {
            ra0 = *(const float4*)&A[(size_t)(m0 + srow) * lda + k0 + 16 + skb];
            ra1 = *(const float4*)&A[(size_t)(m0 + srow) * lda + k0 + 16 + skb + 4];
            if (wact) {
                rw0 = *(const float4*)&W[(size_t)(n0 + srow) * ldw + k0 + 16 + skb];
                rw1 = *(const float4*)&W[(size_t)(n0 + srow) * ldw + k0 + 16 + skb + 4];
            }
        }
        uint4 Af[4];
        Af[0] = *(const uint4*)&As[wm + g     ][4 * t];
        Af[1] = *(const uint4*)&As[wm + g + 8 ][4 * t];
        Af[2] = *(const uint4*)&As[wm + g + 16][4 * t];
        Af[3] = *(const uint4*)&As[wm + g + 24][4 * t];
        #pragma unroll
        for (int nt = 0; nt < NT; nt++) {
            uint4 Bf = *(const uint4*)&Ws[wn + 8 * nt + g][4 * t];
            mma_tf32(acc[0][nt], Af[0].x, Af[1].x, Af[0].y, Af[1].y, Bf.x, Bf.y);
            mma_tf32(acc[1][nt], Af[2].x, Af[3].x, Af[2].y, Af[3].y, Bf.x, Bf.y);
            mma_tf32(acc[0][nt], Af[0].z, Af[1].z, Af[0].w, Af[1].w, Bf.z, Bf.w);
            mma_tf32(acc[1][nt], Af[2].z, Af[3].z, Af[2].w, Af[3].w, Bf.z, Bf.w);
        }
        __syncthreads();
    }

    #pragma unroll
    for (int mt = 0; mt < 2; mt++) {
        const int r0 = m0 + wm + 16 * mt + g;
        #pragma unroll
        for (int nt = 0; nt < NT; nt++) {
            const int n = n0 + wn + 8 * nt + 2 * t;
            #pragma unroll
            for (int half = 0; half < 2; half++) {
                const int r = r0 + 8 * half;
                const size_t ro = (size_t)r * ldc;
                float2 v = { acc[mt][nt][2 * half], acc[mt][nt][2 * half + 1] };
                v.x *= alpha; v.y *= alpha;
                if (bias) { v.x += bias[n]; v.y += bias[n + 1]; }
                if (EPI == 1) { v.x = fmaxf(v.x, 0.f); v.y = fmaxf(v.y, 0.f); }
                if (EPI == 2) { v.x += res[ro + n]; v.y += res[ro + n + 1]; }
                *(float2*)&C[ro + n] = v;
            }
        }
    }
}

// ================= fused flash attention (tf32 MMA, online softmax) =================
// grid (16 q-tiles, 8 heads), 256 threads (8 warps x 16 q-rows).
// qkv layout: [token][1536] with q at +0, k at +512, v at +1024 (per head h: +h*64).
// Output ctx -> outc[token][h*64 + c].
#define KSTRIDE 68
#define VSTRIDE 132
#define SMEM_ATTN ((128 * KSTRIDE + 64 * VSTRIDE) * 4)

__global__ __launch_bounds__(256)
void attn_fused(const float* __restrict__ qkv, float* __restrict__ outc)
{
    extern __shared__ float smf[];
    float* Ksm = smf;                    // [128][KSTRIDE] perm-k layout (also Q staging)
    float* Vt  = smf + 128 * KSTRIDE;    // [64][VSTRIDE]  transposed V, perm-k layout

    const int tid = threadIdx.x;
    const int w = tid >> 5, ln = tid & 31, g = ln >> 2, t = ln & 3;
    const int h = blockIdx.y;
    const int q0 = blockIdx.x * 128;
    const int srow = tid >> 1, shalf = (tid & 1) * 32;

    // ---- stage Q (pre-scaled by 1/8) into Ksm, extract per-warp A-fragments ----
    {
        const float* qp = qkv + (size_t)(q0 + srow) * 1536 + h * 64 + shalf;
        #pragma unroll
        for (int i = 0; i < 8; i++) {
            float4 v = *(const float4*)(qp + 4 * i);
            int c = shalf + 4 * i;
            int grp = c >> 4, a = (c >> 2) & 3;
            float* dst = Ksm + srow * KSTRIDE + grp * 16;
            dst[a]      = to_tf32(v.x * 0.125f);
            dst[4 + a]  = to_tf32(v.y * 0.125f);
            dst[8 + a]  = to_tf32(v.z * 0.125f);
            dst[12 + a] = to_tf32(v.w * 0.125f);
        }
    }
    __syncthreads();
    uint4 qa0[4], qa1[4];
    #pragma unroll
    for (int grp = 0; grp < 4; grp++) {
        qa0[grp] = *(const uint4*)(Ksm + (16 * w + g)     * KSTRIDE + grp * 16 + 4 * t);
        qa1[grp] = *(const uint4*)(Ksm + (16 * w + g + 8) * KSTRIDE + grp * 16 + 4 * t);
    }

    float m0r = -1e30f, m1r = -1e30f, l0r = 0.f, l1r = 0.f;
    float o[8][4];
    #pragma unroll
    for (int nt = 0; nt < 8; nt++)
        #pragma unroll
        for (int i = 0; i < 4; i++) o[nt][i] = 0.f;

    for (int kt = 0; kt < 16; kt++) {
        __syncthreads();
        // ---- stage K tile ----
        {
            const float* kp = qkv + (size_t)(kt * 128 + srow) * 1536 + 512 + h * 64 + shalf;
            #pragma unroll
            for (int i = 0; i < 8; i++) {
                float4 v = *(const float4*)(kp + 4 * i);
                int c = shalf + 4 * i;
                int grp = c >> 4, a = (c >> 2) & 3;
                float* dst = Ksm + srow * KSTRIDE + grp * 16;
                dst[a]      = to_tf32(v.x);
                dst[4 + a]  = to_tf32(v.y);
                dst[8 + a]  = to_tf32(v.z);
                dst[12 + a] = to_tf32(v.w);
            }
        }
        // ---- stage V tile transposed ----
        {
            const float* vp = qkv + (size_t)(kt * 128 + srow) * 1536 + 1024 + h * 64 + shalf;
            const int grp = srow >> 4, lk = srow & 15;
            const int pos = grp * 16 + (lk & 3) * 4 + (lk >> 2);
            #pragma unroll
            for (int i = 0; i < 8; i++) {
                float4 v = *(const float4*)(vp + 4 * i);
                int n = shalf + 4 * i;
                Vt[(n + 0) * VSTRIDE + pos] = to_tf32(v.x);
                Vt[(n + 1) * VSTRIDE + pos] = to_tf32(v.y);
                Vt[(n + 2) * VSTRIDE + pos] = to_tf32(v.z);
                Vt[(n + 3) * VSTRIDE + pos] = to_tf32(v.w);
            }
        }
        __syncthreads();

        // ---- S = Q @ K^T  (16 rows x 128 keys per warp) ----
        float s[16][4];
        #pragma unroll
        for (int nt = 0; nt < 16; nt++)
            #pragma unroll
            for (int i = 0; i < 4; i++) s[nt][i] = 0.f;
        #pragma unroll
        for (int grp = 0; grp < 4; grp++) {
            #pragma unroll
            for (int nt = 0; nt < 16; nt++) {
                uint4 Bf = *(const uint4*)(Ksm + (8 * nt + g) * KSTRIDE + grp * 16 + 4 * t);
                mma_tf32(s[nt], qa0[grp].x, qa1[grp].x, qa0[grp].y, qa1[grp].y, Bf.x, Bf.y);
                mma_tf32(s[nt], qa0[grp].z, qa1[grp].z, qa0[grp].w, qa1[grp].w, Bf.z, Bf.w);
            }
        }

        // ---- online softmax (rows g -> regs 0,1 ; g+8 -> regs 2,3) ----
        float mx0 = -1e30f, mx1 = -1e30f;
        #pragma unroll
        for (int nt = 0; nt < 16; nt++) {
            mx0 = fmaxf(mx0, fmaxf(s[nt][0], s[nt][1]));
            mx1 = fmaxf(mx1, fmaxf(s[nt][2], s[nt][3]));
        }
        mx0 = fmaxf(mx0, __shfl_xor_sync(0xffffffffu, mx0, 1));
        mx0 = fmaxf(mx0, __shfl_xor_sync(0xffffffffu, mx0, 2));
        mx1 = fmaxf(mx1, __shfl_xor_sync(0xffffffffu, mx1, 1));
        mx1 = fmaxf(mx1, __shfl_xor_sync(0xffffffffu, mx1, 2));
        const float mn0 = fmaxf(m0r, mx0), mn1 = fmaxf(m1r, mx1);
        const float al0 = __expf(m0r - mn0), al1 = __expf(m1r - mn1);
        m0r = mn0; m1r = mn1;
        float sum0 = 0.f, sum1 = 0.f;
        #pragma unroll
        for (int nt = 0; nt < 16; nt++) {
            float p0 = __expf(s[nt][0] - mn0);
            float p1 = __expf(s[nt][1] - mn0);
            float p2 = __expf(s[nt][2] - mn1);
            float p3 = __expf(s[nt][3] - mn1);
            sum0 += p0 + p1; sum1 += p2 + p3;
            s[nt][0] = to_tf32(p0); s[nt][1] = to_tf32(p1);
            s[nt][2] = to_tf32(p2); s[nt][3] = to_tf32(p3);
        }
        sum0 += __shfl_xor_sync(0xffffffffu, sum0, 1);
        sum0 += __shfl_xor_sync(0xffffffffu, sum0, 2);
        sum1 += __shfl_xor_sync(0xffffffffu, sum1, 1);
        sum1 += __shfl_xor_sync(0xffffffffu, sum1, 2);
        l0r = l0r * al0 + sum0;
        l1r = l1r * al1 + sum1;
        #pragma unroll
        for (int nt = 0; nt < 8; nt++) {
            o[nt][0] *= al0; o[nt][1] *= al0;
            o[nt][2] *= al1; o[nt][3] *= al1;
        }

        // ---- O += P @ V ----
        const int srcA = (ln & 28) | (t >> 1);
        const int srcB = srcA + 2;
        #pragma unroll
        for (int grp = 0; grp < 8; grp++) {
            uint4 Bv[8];
            #pragma unroll
            for (int nt = 0; nt < 8; nt++)
                Bv[nt] = *(const uint4*)(Vt + (8 * nt + g) * VSTRIDE + grp * 16 + 4 * t);
            #pragma unroll
            for (int half = 0; half < 2; half++) {
                const int kc = 2 * grp + half;
                float x0 = __shfl_sync(0xffffffffu, s[kc][0], srcA);
                float x1 = __shfl_sync(0xffffffffu, s[kc][1], srcA);
                float y0 = __shfl_sync(0xffffffffu, s[kc][2], srcA);
                float y1 = __shfl_sync(0xffffffffu, s[kc][3], srcA);
                float z0 = __shfl_sync(0xffffffffu, s[kc][0], srcB);
                float z1 = __shfl_sync(0xffffffffu, s[kc][1], srcB);
                float u0 = __shfl_sync(0xffffffffu, s[kc][2], srcB);
                float u1 = __shfl_sync(0xffffffffu, s[kc][3], srcB);
                unsigned a0 = __float_as_uint((t & 1) ? x1 : x0);
                unsigned a1 = __float_as_uint((t & 1) ? y1 : y0);
                unsigned a2 = __float_as_uint((t & 1) ? z1 : z0);
                unsigned a3 = __float_as_uint((t & 1) ? u1 : u0);
                #pragma unroll
                for (int nt = 0; nt < 8; nt++) {
                    unsigned b0 = half ? Bv[nt].z : Bv[nt].x;
                    unsigned b1 = half ? Bv[nt].w : Bv[nt].y;
                    mma_tf32(o[nt], a0, a1, a2, a3, b0, b1);
                }
            }
        }
    }

    // ---- epilogue: O /= l, write ctx ----
    const float inv0 = 1.0f / l0r, inv1 = 1.0f / l1r;
    #pragma unroll
    for (int nt = 0; nt < 8; nt++) {
        const int n = h * 64 + 8 * nt + 2 * t;
        const size_t r0 = (size_t)(q0 + 16 * w + g) * D_;
        const size_t r1 = (size_t)(q0 + 16 * w + g + 8) * D_;
        float2 v0 = { o[nt][0] * inv0, o[nt][1] * inv0 };
        float2 v1 = { o[nt][2] * inv1, o[nt][3] * inv1 };
        *(float2*)&outc[r0 + n] = v0;
        *(float2*)&outc[r1 + n] = v1;
    }
}

// ---------------- per-row normalize (LN if AFFINE, InstanceNorm otherwise) ----------------
template<int N, bool AFFINE, bool ADD>
__global__ __launch_bounds__(128)
void rownorm(const float* __restrict__ src, const float* __restrict__ addv,
             const float* __restrict__ w, const float* __restrict__ bb,
             float* __restrict__ dst, float* __restrict__ dst2)
{
    constexpr int NPT = N / 128;
    const size_t base = (size_t)blockIdx.x * N;
    const int t = threadIdx.x;
    float v[NPT];
    float s = 0.f;
    #pragma unroll
    for (int i = 0; i < NPT; i++) { v[i] = src[base + t + i * 128]; s += v[i]; }
    __shared__ float sm[4];
    #pragma unroll
    for (int o = 16; o > 0; o >>= 1) s += __shfl_xor_sync(0xffffffffu, s, o);
    if ((t & 31) == 0) sm[t >> 5] = s;
    __syncthreads();
    s = sm[0] + sm[1] + sm[2] + sm[3];
    const float mean = s * (1.0f / N);
    float q = 0.f;
    #pragma unroll
    for (int i = 0; i < NPT; i++) { float d = v[i] - mean; q += d * d; }
    __syncthreads();
    #pragma unroll
    for (int o = 16; o > 0; o >>= 1) q += __shfl_xor_sync(0xffffffffu, q, o);
    if ((t & 31) == 0) sm[t >> 5] = q;
    __syncthreads();
    q = sm[0] + sm[1] + sm[2] + sm[3];
    const float r = rsqrtf(q * (1.0f / N) + EPSF);
    #pragma unroll
    for (int i = 0; i < NPT; i++) {
        int c = t + i * 128;
        float y = (v[i] - mean) * r;
        if (AFFINE) y = y * w[c] + bb[c];
        if (ADD)    y += addv[base + c];
        dst[base + c] = y;
        if (dst2) dst2[base + c] = y;
    }
}

// ---------------- cdist to prototypes, min over P, logits ----------------
__global__ __launch_bounds__(128)
void cdist_logits(const float* __restrict__ z, const float* __restrict__ hi,
                  const float* __restrict__ neg, float* __restrict__ out)
{
    __shared__ float zr[Q_];
    __shared__ float dist[128];
    const int b = blockIdx.x, t = threadIdx.x;
    zr[t] = z[(size_t)b * Q_ + t];
    dist[t] = 3.4e38f;
    __syncthreads();
    if (t < P_) {
        const float* p = hi + (size_t)t * Q_;
        float s = 0.f;
        #pragma unroll 8
        for (int d = 0; d < Q_; d++) { float df = zr[d] - p[d]; s = fmaf(df, df, s); }
        dist[t] = sqrtf(s);
    } else if (t >= 64 && t < 64 + P_) {
        const float* p = neg + (size_t)(t - 64) * Q_;
        float s = 0.f;
        #pragma unroll 8
        for (int d = 0; d < Q_; d++) { float df = zr[d] - p[d]; s = fmaf(df, df, s); }
        dist[t] = sqrtf(s);
    }
    __syncthreads();
    if (t == 0) {
        float m = 3.4e38f;
        for (int i = 0; i < P_; i++) m = fminf(m, dist[i]);
        out[b * 2 + 1] = -m;      // -positive_dist
    }
    if (t == 32) {
        float m = 3.4e38f;
        for (int i = 0; i < P_; i++) m = fminf(m, dist[64 + i]);
        out[b * 2 + 0] = -m;      // -negative_dist
    }
}

// ---------------- host driver ----------------
extern "C" void kernel_launch(void* const* d_in, const int* in_sizes, int n_in,
                              void* d_out, int out_size)
{
    const float* x        = (const float*)d_in[0];
    const float* reduce_w = (const float*)d_in[1];
    const float* reduce_b = (const float*)d_in[2];
    const float* in_w     = (const float*)d_in[3];
    const float* in_b     = (const float*)d_in[4];
    const float* out_w    = (const float*)d_in[5];
    const float* out_b    = (const float*)d_in[6];
    const float* ff1_w    = (const float*)d_in[7];
    const float* ff1_b    = (const float*)d_in[8];
    const float* ff2_w    = (const float*)d_in[9];
    const float* ff2_b    = (const float*)d_in[10];
    const float* ln1_w    = (const float*)d_in[11];
    const float* ln1_b    = (const float*)d_in[12];
    const float* ln2_w    = (const float*)d_in[13];
    const float* ln2_b    = (const float*)d_in[14];
    const float* mlp_w1   = (const float*)d_in[15];
    const float* mlp_b1   = (const float*)d_in[16];
    const float* mlp_w2   = (const float*)d_in[17];
    const float* mlp_b2   = (const float*)d_in[18];
    const float* mlp_w3   = (const float*)d_in[19];
    const float* mlp_b3   = (const float*)d_in[20];
    const float* highlights = (const float*)d_in[21];
    const float* negatives  = (const float*)d_in[22];
    float* out = (float*)d_out;

    float *feat0, *feat, *buf1, *buf2, *qkv, *z;
    cudaGetSymbolAddress((void**)&feat0, g_feat0);
    cudaGetSymbolAddress((void**)&feat,  g_feat);
    cudaGetSymbolAddress((void**)&buf1,  g_buf1);
    cudaGetSymbolAddress((void**)&buf2,  g_buf2);
    cudaGetSymbolAddress((void**)&qkv,   g_qkv);
    cudaGetSymbolAddress((void**)&z,     g_z);

    static int smem_set = 0;
    if (!smem_set) {
        cudaFuncSetAttribute(attn_fused, cudaFuncAttributeMaxDynamicSharedMemorySize,
                             SMEM_ATTN);
        smem_set = 1;
    }

    const dim3 blk(256);

    // feat0 = inorm(x @ reduce_w^T + b);  feat = feat0
    gemm_mma_tn<64, 0><<<dim3(D_ / 64, B_ / 128, 1), blk>>>(
        x, reduce_w, reduce_b, nullptr, buf1, DIN_, DIN_, DIN_, D_, 0, 0, 0, 1.f);
    rownorm<D_, false, false><<<B_, 128>>>(buf1, nullptr, nullptr, nullptr, feat0, feat);

    for (int l = 0; l < L_; l++) {
        // qkv = feat @ in_w^T + in_b
        gemm_mma_tn<128, 0><<<dim3(3 * D_ / 128, B_ / 128, 1), blk>>>(
            feat, in_w + (size_t)l * 3 * D_ * D_, in_b + l * 3 * D_, nullptr, qkv,
            D_, D_, D_, 3 * D_, 0, 0, 0, 1.f);
        // fused attention -> buf2 (ctx)
        attn_fused<<<dim3(B_ / 128, H_), blk, SMEM_ATTN>>>(qkv, buf2);
        // attn_out + residual -> buf1 ; LN1 -> feat
        gemm_mma_tn<64, 2><<<dim3(D_ / 64, B_ / 128, 1), blk>>>(
            buf2, out_w + (size_t)l * D_ * D_, out_b + l * D_, feat, buf1,
            D_, D_, D_, D_, 0, 0, 0, 1.f);
        rownorm<D_, true, false><<<B_, 128>>>(buf1, nullptr, ln1_w + l * D_, ln1_b + l * D_, feat, nullptr);
        // FFN
        gemm_mma_tn<64, 1><<<dim3(D_ / 64, B_ / 128, 1), blk>>>(
            feat, ff1_w + (size_t)l * D_ * D_, ff1_b + l * D_, nullptr, buf2,
            D_, D_, D_, D_, 0, 0, 0, 1.f);
        gemm_mma_tn<64, 2><<<dim3(D_ / 64, B_ / 128, 1), blk>>>(
            buf2, ff2_w + (size_t)l * D_ * D_, ff2_b + l * D_, feat, buf1,
            D_, D_, D_, D_, 0, 0, 0, 1.f);
        rownorm<D_, true, false><<<B_, 128>>>(buf1, nullptr, ln2_w + l * D_, ln2_b + l * D_, feat, nullptr);
    }

    // feat = feat0 + inorm(feat)  -> buf1
    rownorm<D_, false, true><<<B_, 128>>>(feat, feat0, nullptr, nullptr, buf1, nullptr);

    // MLP: 512 -> 512 -> 512 -> 128
    gemm_mma_tn<64, 1><<<dim3(D_ / 64, B_ / 128, 1), blk>>>(
        buf1, mlp_w1, mlp_b1, nullptr, buf2, D_, D_, D_, D_, 0, 0, 0, 1.f);
    gemm_mma_tn<64, 1><<<dim3(D_ / 64, B_ / 128, 1), blk>>>(
        buf2, mlp_w2, mlp_b2, nullptr, buf1, D_, D_, D_, D_, 0, 0, 0, 1.f);
    gemm_mma_tn<64, 0><<<dim3(Q_ / 64, B_ / 128, 1), blk>>>(
        buf1, mlp_w3, mlp_b3, nullptr, buf2, D_, D_, D_, Q_, 0, 0, 0, 1.f);
    rownorm<Q_, false, false><<<B_, 128>>>(buf2, nullptr, nullptr, nullptr, z, nullptr);

    cdist_logits<<<B_, 128>>>(z, highlights, negatives, out);
}